// round 2
// baseline (speedup 1.0000x reference)
#include <cuda_runtime.h>
#include <cuda_bf16.h>

// RankedListLoss fused kernel, round 2: fp32 SGEMM-style tiles, symmetric
// upper-triangular traversal (half the N^2 work), fused epilogue.
//
// dist(i,j) = sq_i + sq_j - 2*dot(e_i, e_j)
// pos_loss  = sum over {same class, i!=j, dist > 0.8} of (dist - 0.8)
// neg: per class c: wsum_c = sum_{i:lab=c, j:lab!=c, dist<1.2} exp(10*(1.2-dist))
//      num_c = same with extra (1.2-dist) factor; neg_loss = sum_c num_c/wsum_c (wsum>0)
// out = pos_loss + neg_loss, out[1] = N

#define NMAX 8192
#define DIM 128
#define BM 128
#define KC 16
#define APM 0.8f     /* alpha - margin */
#define ALPHAC 1.2f
#define TC 10.0f

__device__ float  d_sq[NMAX];
__device__ int    d_lab[NMAX];
__device__ int    d_mode64;
__device__ double d_pos;
__device__ float  d_cw[64];
__device__ float  d_cn[64];

// ---------------------------------------------------------------------------
// Setup: zero accumulators, detect label dtype (int32 vs int64 little-endian).
__global__ void k_setup(const int* labraw, int n) {
    int t = threadIdx.x;
    if (t == 0) {
        int allz = 1;
        int lim = (n < 32 ? n : 32);          // probe up to 32 elements' odd slots
        for (int i = 0; i < lim; i++) allz &= (labraw[2 * i + 1] == 0);
        d_mode64 = allz;   // all odd int32 slots zero => int64 layout
        d_pos = 0.0;
    }
    if (t < 64) { d_cw[t] = 0.0f; d_cn[t] = 0.0f; }
}

// ---------------------------------------------------------------------------
// Prep: squared norms + normalized labels.
__global__ void k_prep(const float* __restrict__ emb, const void* labraw, int n) {
    int i = blockIdx.x * blockDim.x + threadIdx.x;
    if (i >= n) return;
    int lab = d_mode64 ? ((const int2*)labraw)[i].x : ((const int*)labraw)[i];
    d_lab[i] = lab;
    const float4* r = (const float4*)(emb + (size_t)i * DIM);
    float s = 0.0f;
    #pragma unroll
    for (int q = 0; q < DIM / 4; q++) {
        float4 v = r[q];
        s += v.x * v.x + v.y * v.y + v.z * v.z + v.w * v.w;
    }
    d_sq[i] = s;
}

// ---------------------------------------------------------------------------
// Main: upper-triangular 128x128 tiles, 256 threads, 8x8 microtile, fused epilogue.
__global__ __launch_bounds__(256) void k_main(const float* __restrict__ emb, int n) {
    __shared__ float As[KC][BM];
    __shared__ float Bs[KC][BM];
    __shared__ float red[256];

    const int NT = n / BM;
    // closed-form decode: linear block id -> (ti, tj) with ti <= tj
    // bid = ti*NT - ti*(ti-1)/2 + (tj - ti)
    {
    }
    int bid = blockIdx.x;
    float fN = (float)NT;
    // solve ti from bid: ti = floor( ( (2N+1) - sqrt((2N+1)^2 - 8*bid) ) / 2 )
    float disc = (2.0f * fN + 1.0f) * (2.0f * fN + 1.0f) - 8.0f * (float)bid;
    int ti = (int)(((2.0f * fN + 1.0f) - sqrtf(disc)) * 0.5f);
    // fix up potential fp rounding
    while (ti > 0 && bid < ti * NT - (ti * (ti - 1)) / 2) ti--;
    while (bid >= (ti + 1) * NT - ((ti + 1) * ti) / 2) ti++;
    int tj = ti + (bid - (ti * NT - (ti * (ti - 1)) / 2));

    const int rowBase = ti * BM;
    const int colBase = tj * BM;
    const int t  = threadIdx.x;
    const int tx = t & 15;
    const int ty = t >> 4;

    float acc[8][8];
    #pragma unroll
    for (int r = 0; r < 8; r++)
        #pragma unroll
        for (int c = 0; c < 8; c++) acc[r][c] = 0.0f;

    const int kq = t & 3;    // which float4 within the KC=16 chunk
    const int m  = t >> 2;   // row within tile half (0..63)

    for (int kc = 0; kc < DIM; kc += KC) {
        // global loads (before the barrier, to overlap with prior compute)
        float4 va  = ((const float4*)(emb + (size_t)(rowBase + m)      * DIM + kc))[kq];
        float4 va2 = ((const float4*)(emb + (size_t)(rowBase + m + 64) * DIM + kc))[kq];
        float4 vb  = ((const float4*)(emb + (size_t)(colBase + m)      * DIM + kc))[kq];
        float4 vb2 = ((const float4*)(emb + (size_t)(colBase + m + 64) * DIM + kc))[kq];

        __syncthreads();   // previous iteration's compute done
        int kb = kq * 4;
        As[kb + 0][m] = va.x;  As[kb + 1][m] = va.y;  As[kb + 2][m] = va.z;  As[kb + 3][m] = va.w;
        As[kb + 0][m + 64] = va2.x; As[kb + 1][m + 64] = va2.y; As[kb + 2][m + 64] = va2.z; As[kb + 3][m + 64] = va2.w;
        Bs[kb + 0][m] = vb.x;  Bs[kb + 1][m] = vb.y;  Bs[kb + 2][m] = vb.z;  Bs[kb + 3][m] = vb.w;
        Bs[kb + 0][m + 64] = vb2.x; Bs[kb + 1][m + 64] = vb2.y; Bs[kb + 2][m + 64] = vb2.z; Bs[kb + 3][m + 64] = vb2.w;
        __syncthreads();

        #pragma unroll
        for (int k = 0; k < KC; k++) {
            float4 a0 = *(const float4*)&As[k][ty * 8];
            float4 a1 = *(const float4*)&As[k][ty * 8 + 4];
            float4 b0 = *(const float4*)&Bs[k][tx * 8];
            float4 b1 = *(const float4*)&Bs[k][tx * 8 + 4];
            float a[8] = {a0.x, a0.y, a0.z, a0.w, a1.x, a1.y, a1.z, a1.w};
            float b[8] = {b0.x, b0.y, b0.z, b0.w, b1.x, b1.y, b1.z, b1.w};
            #pragma unroll
            for (int r = 0; r < 8; r++)
                #pragma unroll
                for (int c = 0; c < 8; c++)
                    acc[r][c] += a[r] * b[c];
        }
    }

    // ---- epilogue ----
    float sqi[8], sqj[8];
    int   li[8],  lj[8];
    #pragma unroll
    for (int r = 0; r < 8; r++) {
        int gi = rowBase + ty * 8 + r;
        sqi[r] = d_sq[gi]; li[r] = d_lab[gi];
    }
    #pragma unroll
    for (int c = 0; c < 8; c++) {
        int gj = colBase + tx * 8 + c;
        sqj[c] = d_sq[gj]; lj[c] = d_lab[gj];
    }

    const bool diag = (ti == tj);
    float pos = 0.0f;
    #pragma unroll
    for (int r = 0; r < 8; r++) {
        int gi = rowBase + ty * 8 + r;
        #pragma unroll
        for (int c = 0; c < 8; c++) {
            int gj = colBase + tx * 8 + c;
            if (diag && gj <= gi) continue;   // strict upper triangle on diagonal tiles
            float dist = sqi[r] + sqj[c] - 2.0f * acc[r][c];
            if (li[r] == lj[c]) {
                if (dist > APM) pos += dist - APM;
            } else if (dist < ALPHAC) {
                float gap = ALPHAC - dist;
                float w = expf(TC * gap);
                // pair (i,j) feeds row i (class li) and row j (class lj)
                atomicAdd(&d_cw[li[r]], w);
                atomicAdd(&d_cn[li[r]], gap * w);
                atomicAdd(&d_cw[lj[c]], w);
                atomicAdd(&d_cn[lj[c]], gap * w);
            }
        }
    }
    pos *= 2.0f;   // each unordered pair appears twice in the reference sum

    // block reduction -> one double atomic per block
    red[t] = pos;
    __syncthreads();
    for (int s = 128; s > 0; s >>= 1) {
        if (t < s) red[t] += red[t + s];
        __syncthreads();
    }
    if (t == 0) atomicAdd(&d_pos, (double)red[0]);
}

// ---------------------------------------------------------------------------
__global__ void k_fin(float* out, int out_size, int n) {
    double neg = 0.0;
    for (int c = 0; c < 64; c++) {
        float w = d_cw[c];
        if (w > 0.0f) neg += (double)(d_cn[c] / w);
    }
    out[0] = (float)(d_pos + neg);
    if (out_size > 1) out[1] = (float)n;
}

// ---------------------------------------------------------------------------
extern "C" void kernel_launch(void* const* d_in, const int* in_sizes, int n_in,
                              void* d_out, int out_size) {
    const float* emb = (const float*)d_in[0];
    const void*  lab = d_in[1];
    int n = in_sizes[1];               // 8192
    float* out = (float*)d_out;

    k_setup<<<1, 64>>>((const int*)lab, n);
    k_prep<<<(n + 255) / 256, 256>>>(emb, lab, n);

    int nt = n / BM;
    int nblocks = nt * (nt + 1) / 2;   // upper-triangular tile pairs
    k_main<<<nblocks, 256>>>(emb, n);

    k_fin<<<1, 1>>>(out, out_size, n);
}

// round 4
// speedup vs baseline: 2.5357x; 2.5357x over previous
#include <cuda_runtime.h>
#include <cuda_bf16.h>
#include <cstdint>

// RankedListLoss, round 4: mma.sync bf16 (sm_80-family PTX, legal on compute_103)
// gram GEMM on upper-triangular 128x128 tiles, fused epilogue.
//
// dist(i,j) = sq_i + sq_j - 2*dot(e_i,e_j)   (sq in fp32, dot via bf16 tensor cores)
// pos_loss  = sum {same class, i!=j, dist > 0.8} (dist - 0.8)
// neg: per class, softmax-weighted gap over cross-class pairs with dist < 1.2
// out[0] = pos + neg, out[1] = N

#define NMAX 8192
#define DIM 128
#define BM 128
#define LDT 136            /* padded smem row stride in bf16 elems */
#define APM 0.8f
#define ALPHAC 1.2f
#define TC 10.0f

__device__ float          d_sq[NMAX];
__device__ int            d_lab[NMAX];
__device__ __nv_bfloat16  d_ebf[NMAX * DIM];
__device__ int            d_mode64;
__device__ double         d_pos;
__device__ float          d_cw[64];
__device__ float          d_cn[64];

// ---------------------------------------------------------------------------
__global__ void k_setup(const int* labraw, int n) {
    int t = threadIdx.x;
    if (t == 0) {
        int allz = 1;
        int lim = (n < 32 ? n : 32);
        for (int i = 0; i < lim; i++) allz &= (labraw[2 * i + 1] == 0);
        d_mode64 = allz;   // all odd int32 slots zero => labels are int64
        d_pos = 0.0;
    }
    if (t < 64) { d_cw[t] = 0.0f; d_cn[t] = 0.0f; }
}

// Squared norms (fp32), normalized labels, bf16 copy of embeddings.
__global__ void k_prep(const float* __restrict__ emb, const void* labraw, int n) {
    int i = blockIdx.x * blockDim.x + threadIdx.x;
    if (i >= n) return;
    d_lab[i] = d_mode64 ? ((const int2*)labraw)[i].x : ((const int*)labraw)[i];
    const float4* r = (const float4*)(emb + (size_t)i * DIM);
    __nv_bfloat16* eb = d_ebf + (size_t)i * DIM;
    float s = 0.0f;
    #pragma unroll
    for (int q = 0; q < DIM / 4; q++) {
        float4 v = r[q];
        s += v.x * v.x + v.y * v.y + v.z * v.z + v.w * v.w;
        eb[q * 4 + 0] = __float2bfloat16(v.x);
        eb[q * 4 + 1] = __float2bfloat16(v.y);
        eb[q * 4 + 2] = __float2bfloat16(v.z);
        eb[q * 4 + 3] = __float2bfloat16(v.w);
    }
    d_sq[i] = s;
}

// ---------------------------------------------------------------------------
__device__ __forceinline__ void mma_bf16(float* d, const uint32_t* a, const uint32_t* b) {
    asm volatile(
        "mma.sync.aligned.m16n8k16.row.col.f32.bf16.bf16.f32 "
        "{%0,%1,%2,%3}, {%4,%5,%6,%7}, {%8,%9}, {%0,%1,%2,%3};"
        : "+f"(d[0]), "+f"(d[1]), "+f"(d[2]), "+f"(d[3])
        : "r"(a[0]), "r"(a[1]), "r"(a[2]), "r"(a[3]), "r"(b[0]), "r"(b[1]));
}

// smem layout (dynamic)
#define SM_RED 0                   /* 256 floats */
#define SM_SQI 1024                /* 128 floats */
#define SM_SQJ 1536
#define SM_LI  2048                /* 128 ints */
#define SM_LJ  2560
#define SM_A   3072                /* 128 x LDT bf16 = 34816 B */
#define SM_B   (SM_A + BM * LDT * 2)
#define SM_TOTAL (SM_B + BM * LDT * 2)

__global__ __launch_bounds__(256, 2) void k_main(int n) {
    extern __shared__ char smem[];
    __nv_bfloat16* As = (__nv_bfloat16*)(smem + SM_A);
    __nv_bfloat16* Bs = (__nv_bfloat16*)(smem + SM_B);
    float* sqi_s = (float*)(smem + SM_SQI);
    float* sqj_s = (float*)(smem + SM_SQJ);
    int*   li_s  = (int*)(smem + SM_LI);
    int*   lj_s  = (int*)(smem + SM_LJ);

    const int t = threadIdx.x, w = t >> 5, lane = t & 31;
    const int warp_m = w & 1;          // 2 row groups of 64
    const int warp_n = w >> 1;         // 4 col groups of 32

    // triangular decode: bid -> (ti, tj), ti <= tj
    const int NT = n / BM;
    int bid = blockIdx.x;
    float fN = (float)NT;
    float disc = (2.0f * fN + 1.0f) * (2.0f * fN + 1.0f) - 8.0f * (float)bid;
    int ti = (int)(((2.0f * fN + 1.0f) - sqrtf(disc)) * 0.5f);
    while (ti > 0 && bid < ti * NT - (ti * (ti - 1)) / 2) ti--;
    while (bid >= (ti + 1) * NT - ((ti + 1) * ti) / 2) ti++;
    int tj = ti + (bid - (ti * NT - (ti * (ti - 1)) / 2));
    const int rowBase = ti * BM, colBase = tj * BM;

    // ---- load whole-K tiles into padded smem (+ stage sq/lab) ----
    {
        const uint4* gA = (const uint4*)(d_ebf + (size_t)rowBase * DIM);
        const uint4* gB = (const uint4*)(d_ebf + (size_t)colBase * DIM);
        #pragma unroll
        for (int i = 0; i < 8; i++) {
            int idx = t + i * 256;                 // 0..2047
            int row = idx >> 4, c8 = idx & 15;     // 16 uint4 per 128-elem row
            uint4 va = gA[row * 16 + c8];
            uint4 vb = gB[row * 16 + c8];
            *(uint4*)(As + row * LDT + c8 * 8) = va;
            *(uint4*)(Bs + row * LDT + c8 * 8) = vb;
        }
        if (t < 128) {
            sqi_s[t] = d_sq[rowBase + t];  li_s[t] = d_lab[rowBase + t];
            sqj_s[t] = d_sq[colBase + t];  lj_s[t] = d_lab[colBase + t];
        }
    }
    __syncthreads();

    // ---- MMA: each warp 64x32, m16n8k16, 8 K-steps ----
    float acc[4][4][4];
    #pragma unroll
    for (int mt = 0; mt < 4; mt++)
        #pragma unroll
        for (int nt = 0; nt < 4; nt++)
            #pragma unroll
            for (int q = 0; q < 4; q++) acc[mt][nt][q] = 0.0f;

    const int arow = warp_m * 64 + (lane >> 2);     // + mt*16 (+8 for a1/a3)
    const int brow = warp_n * 32 + (lane >> 2);     // + nt*8
    const int kcol = (lane & 3) * 2;                // + kstep*16 (+8 for a2/a3, b1)

    #pragma unroll
    for (int ks = 0; ks < 8; ks++) {
        const int k0 = ks * 16 + kcol;
        uint32_t a[4][4], b[4][2];
        #pragma unroll
        for (int mt = 0; mt < 4; mt++) {
            const __nv_bfloat16* p = As + (arow + mt * 16) * LDT + k0;
            a[mt][0] = *(const uint32_t*)p;
            a[mt][1] = *(const uint32_t*)(p + 8 * LDT);
            a[mt][2] = *(const uint32_t*)(p + 8);
            a[mt][3] = *(const uint32_t*)(p + 8 * LDT + 8);
        }
        #pragma unroll
        for (int nt = 0; nt < 4; nt++) {
            const __nv_bfloat16* p = Bs + (brow + nt * 8) * LDT + k0;
            b[nt][0] = *(const uint32_t*)p;
            b[nt][1] = *(const uint32_t*)(p + 8);
        }
        #pragma unroll
        for (int mt = 0; mt < 4; mt++)
            #pragma unroll
            for (int nt = 0; nt < 4; nt++)
                mma_bf16(acc[mt][nt], a[mt], b[nt]);
    }

    // ---- fused epilogue ----
    const bool diag = (ti == tj);
    float pos = 0.0f;
    #pragma unroll
    for (int mt = 0; mt < 4; mt++) {
        #pragma unroll
        for (int nt = 0; nt < 4; nt++) {
            #pragma unroll
            for (int q = 0; q < 4; q++) {
                int i_loc = warp_m * 64 + mt * 16 + (lane >> 2) + (q >> 1) * 8;
                int j_loc = warp_n * 32 + nt * 8 + (lane & 3) * 2 + (q & 1);
                int gi = rowBase + i_loc, gj = colBase + j_loc;
                if (diag && gj <= gi) continue;      // strict upper triangle
                float dist = fmaf(-2.0f, acc[mt][nt][q], sqi_s[i_loc] + sqj_s[j_loc]);
                int li = li_s[i_loc], lj = lj_s[j_loc];
                if (li == lj) {
                    if (dist > APM) pos += dist - APM;
                } else if (dist < ALPHAC) {          // statistically cold branch
                    float gap = ALPHAC - dist;
                    float ww = expf(TC * gap);
                    atomicAdd(&d_cw[li], ww); atomicAdd(&d_cn[li], gap * ww);
                    atomicAdd(&d_cw[lj], ww); atomicAdd(&d_cn[lj], gap * ww);
                }
            }
        }
    }
    pos *= 2.0f;   // each unordered pair appears twice in the reference sum

    // block reduce -> one double atomic
    float* red = (float*)(smem + SM_RED);
    red[t] = pos;
    __syncthreads();
    for (int s = 128; s > 0; s >>= 1) {
        if (t < s) red[t] += red[t + s];
        __syncthreads();
    }
    if (t == 0) atomicAdd(&d_pos, (double)red[0]);
}

// ---------------------------------------------------------------------------
__global__ void k_fin(float* out, int out_size, int n) {
    __shared__ float s[64];
    int t = threadIdx.x;
    float wv = d_cw[t];
    s[t] = (wv > 0.0f) ? (d_cn[t] / wv) : 0.0f;
    __syncthreads();
    if (t < 32) {
        float x = s[t] + s[t + 32];
        #pragma unroll
        for (int o = 16; o > 0; o >>= 1) x += __shfl_down_sync(0xFFFFFFFFu, x, o);
        if (t == 0) {
            out[0] = (float)(d_pos + (double)x);
            if (out_size > 1) out[1] = (float)n;
        }
    }
}

// ---------------------------------------------------------------------------
extern "C" void kernel_launch(void* const* d_in, const int* in_sizes, int n_in,
                              void* d_out, int out_size) {
    const float* emb = (const float*)d_in[0];
    const void*  lab = d_in[1];
    int n = in_sizes[1];               // 8192
    float* out = (float*)d_out;

    cudaFuncSetAttribute(k_main, cudaFuncAttributeMaxDynamicSharedMemorySize, SM_TOTAL);

    k_setup<<<1, 64>>>((const int*)lab, n);
    k_prep<<<(n + 255) / 256, 256>>>(emb, lab, n);

    int nt = n / BM;
    int nblocks = nt * (nt + 1) / 2;
    k_main<<<nblocks, 256, SM_TOTAL>>>(n);

    k_fin<<<1, 64>>>(out, out_size, n);
}